// round 3
// baseline (speedup 1.0000x reference)
#include <cuda_runtime.h>

// Problem constants (fixed shapes)
#define BATCH   2
#define H       64
#define W       64
#define C       128
#define N_IN    (H * W * C)            // 524288
#define N_POOL  ((H/2) * (W/2) * C)    // 131072
#define N_OUT   32

// Output layout (concatenated, all float32):
//   [0, OFF1)       w_zero #1 : 33,554,432
//   [OFF1, OFF2)    b_out_u_  : 64
//   [OFF2, OFF3)    w_zero #2 : 33,554,432
//   [OFF3, TOTAL)   b_out_l_  : 64
#define OFF1    (BATCH * N_IN * N_OUT)         // 33554432
#define OFF2    (OFF1 + BATCH * N_OUT)         // 33554496
#define OFF3    (OFF2 + BATCH * N_IN * N_OUT)  // 67108928
#define TOTAL   (OFF3 + BATCH * N_OUT)         // 67108992
#define TOTAL4  (TOTAL / 4)                    // 16777248 float4s

#define NTHREADS 256
#define ZBLOCKS  1792
#define RBLOCKS  512
#define NBLOCKS  (ZBLOCKS + RBLOCKS)                 // 2304
#define ROWS_TOTAL (BATCH * N_POOL)                  // 262144
#define ROWS_PER_WARP (ROWS_TOTAL / (RBLOCKS * 8))   // 64

// Per-reduce-block partial sums: [rb][0..31]=accu, [rb][32..63]=accl.
// Fully overwritten every call -> deterministic across graph replays.
__device__ float g_partial[RBLOCKS * 64];

// Fused kernel. Roles interleaved by blockIdx so every scheduling wave mixes
// store-blocks (zero-fill) with read-blocks (pool+reduce): per group of 9
// blocks, 2 are reduce, 7 are zero-fill.
__global__ void __launch_bounds__(NTHREADS)
fused_kernel(float* __restrict__ out,
             const float* __restrict__ u_c,
             const float* __restrict__ l_c,
             const float* __restrict__ w_out_u,
             const float* __restrict__ w_out_l) {
    const int bx  = blockIdx.x;
    const int grp = bx / 9;
    const int rem = bx % 9;

    if (rem >= 2) {
        // ---- zero-fill role: float4 grid-stride over the WHOLE output.
        // Bias slots get overwritten by the finalize kernel afterward.
        const int zb = grp * 7 + (rem - 2);          // 0..1791
        float4* o4 = reinterpret_cast<float4*>(out);
        const float4 z = make_float4(0.f, 0.f, 0.f, 0.f);
        const int stride = ZBLOCKS * NTHREADS;
        for (int i = zb * NTHREADS + threadIdx.x; i < TOTAL4; i += stride)
            o4[i] = z;
        return;
    }

    // ---- reduce role ----
    const int rb   = grp * 2 + rem;                  // 0..511
    const int warp = threadIdx.x >> 5;
    const int lane = threadIdx.x & 31;
    const int gw   = rb * 8 + warp;                  // global warp id
    const int r0   = gw * ROWS_PER_WARP;             // first row
    const int b    = r0 >> 17;                       // batch (warp-aligned split)

    float accu = 0.f;
    float accl = 0.f;

    #pragma unroll 4
    for (int i = 0; i < ROWS_PER_WARP; i++) {
        const int r  = r0 + i;                       // global row = b*N_POOL + p
        const int p  = r & (N_POOL - 1);
        const int c  = p & 127;
        const int ow = (p >> 7) & 31;
        const int oh = p >> 12;
        const int base = b * N_IN + oh * (2 * W * C) + ow * (2 * C) + c;

        // fused 2x2 maxpool (lane-uniform broadcast loads, L1-resident lines)
        const float u0 = __ldg(u_c + base);
        const float u1 = __ldg(u_c + base + C);
        const float u2 = __ldg(u_c + base + W * C);
        const float u3 = __ldg(u_c + base + W * C + C);
        const float bu = fmaxf(fmaxf(u0, u1), fmaxf(u2, u3));

        const float l0 = __ldg(l_c + base);
        const float l1 = __ldg(l_c + base + C);
        const float l2 = __ldg(l_c + base + W * C);
        const float l3 = __ldg(l_c + base + W * C + C);
        const float bl = fmaxf(fmaxf(l0, l1), fmaxf(l2, l3));

        // coalesced weight rows: lane = output index o (128B/warp/row, streaming)
        const float wu = __ldg(w_out_u + r * N_OUT + lane);
        const float wl = __ldg(w_out_l + r * N_OUT + lane);

        accu += fmaxf(wu, 0.f) * bu + fminf(wu, 0.f) * bl;
        accl += fmaxf(wl, 0.f) * bl + fminf(wl, 0.f) * bu;
    }

    // block reduction across the 8 warps, then write partials (no atomics)
    __shared__ float su[8][32];
    __shared__ float sl[8][32];
    su[warp][lane] = accu;
    sl[warp][lane] = accl;
    __syncthreads();

    if (warp == 0) {
        float s = 0.f;
        #pragma unroll
        for (int k = 0; k < 8; k++) s += su[k][lane];
        g_partial[rb * 64 + lane] = s;
    } else if (warp == 1) {
        float s = 0.f;
        #pragma unroll
        for (int k = 0; k < 8; k++) s += sl[k][lane];
        g_partial[rb * 64 + 32 + lane] = s;
    }
}

// Finalize: sum the 256 per-block partials for each of the 128 bias outputs,
// add the input bias, overwrite the (previously zero-filled) bias slots.
__global__ void finalize_kernel(float* __restrict__ out,
                                const float* __restrict__ b_out_u,
                                const float* __restrict__ b_out_l) {
    const int t   = threadIdx.x;      // 0..127
    const int o   = t & 31;
    const int b   = (t >> 5) & 1;
    const int sel = t >> 6;           // 0 = upper, 1 = lower

    float s = 0.f;
    const int rb0 = b * (RBLOCKS / 2);
    #pragma unroll 8
    for (int k = 0; k < RBLOCKS / 2; k++)
        s += g_partial[(rb0 + k) * 64 + sel * 32 + o];

    if (sel == 0)
        out[OFF1 + b * N_OUT + o] = s + b_out_u[b * N_OUT + o];
    else
        out[OFF3 + b * N_OUT + o] = s + b_out_l[b * N_OUT + o];
}

extern "C" void kernel_launch(void* const* d_in, const int* in_sizes, int n_in,
                              void* d_out, int out_size) {
    // metadata order: y, x_0, u_c, l_c, w_out_u, b_out_u, w_out_l, b_out_l
    const float* u_c     = (const float*)d_in[2];
    const float* l_c     = (const float*)d_in[3];
    const float* w_out_u = (const float*)d_in[4];
    const float* b_out_u = (const float*)d_in[5];
    const float* w_out_l = (const float*)d_in[6];
    const float* b_out_l = (const float*)d_in[7];
    float* out = (float*)d_out;

    fused_kernel<<<NBLOCKS, NTHREADS>>>(out, u_c, l_c, w_out_u, w_out_l);
    finalize_kernel<<<1, 128>>>(out, b_out_u, b_out_l);
}

// round 4
// speedup vs baseline: 1.1365x; 1.1365x over previous
#include <cuda_runtime.h>

// Problem constants (fixed shapes)
#define BATCH   2
#define H       64
#define W       64
#define C       128
#define N_IN    (H * W * C)            // 524288
#define N_POOL  ((H/2) * (W/2) * C)    // 131072
#define N_OUT   32

// Output layout (concatenated, all float32):
//   [0, OFF1)       w_zero #1 : 33,554,432
//   [OFF1, OFF2)    b_out_u_  : 64
//   [OFF2, OFF3)    w_zero #2 : 33,554,432
//   [OFF3, TOTAL)   b_out_l_  : 64
#define OFF1    (BATCH * N_IN * N_OUT)         // 33554432
#define OFF2    (OFF1 + BATCH * N_OUT)         // 33554496
#define OFF3    (OFF2 + BATCH * N_IN * N_OUT)  // 67108928
#define TOTAL   (OFF3 + BATCH * N_OUT)         // 67108992
#define TOTAL4  (TOTAL / 4)                    // 16777248 float4s

#define NTHREADS   256
#define ZGRID      2048
#define RGRID      2048
#define ROWS_TOTAL (BATCH * N_POOL)                  // 262144
#define WARPS_R    (RGRID * (NTHREADS / 32))         // 16384
#define ROWS_PER_WARP (ROWS_TOTAL / WARPS_R)         // 16
#define ROWS_PER_BLOCK (ROWS_TOTAL / RGRID)          // 128 (batch split is block-aligned)

// Per-reduce-block partials: [blk][0..31]=accu, [blk][32..63]=accl.
// Fully overwritten every call -> deterministic across graph replays.
__device__ float g_partial[RGRID * 64];

// ---------------------------------------------------------------------------
// Phase 1: pure write stream. Zero the whole output (bias slots get
// overwritten by finalize afterward). Unidirectional HBM traffic.
// ---------------------------------------------------------------------------
__global__ void __launch_bounds__(NTHREADS)
zero_kernel(float* __restrict__ out) {
    float4* o4 = reinterpret_cast<float4*>(out);
    const float4 z = make_float4(0.f, 0.f, 0.f, 0.f);
    const int stride = ZGRID * NTHREADS;
    for (int i = blockIdx.x * NTHREADS + threadIdx.x; i < TOTAL4; i += stride)
        o4[i] = z;
}

// ---------------------------------------------------------------------------
// Phase 2: pure read stream, full chip. Fused 2x2 maxpool of u_c/l_c +
// sign-split dot with backward weights. Partials -> g_partial (L2-resident).
// ---------------------------------------------------------------------------
__global__ void __launch_bounds__(NTHREADS)
reduce_kernel(const float* __restrict__ u_c,
              const float* __restrict__ l_c,
              const float* __restrict__ w_out_u,
              const float* __restrict__ w_out_l) {
    const int warp = threadIdx.x >> 5;
    const int lane = threadIdx.x & 31;
    const int gw   = blockIdx.x * 8 + warp;
    const int r0   = gw * ROWS_PER_WARP;
    const int b    = r0 >> 17;                 // batch (131072 rows per batch)

    float accu = 0.f;
    float accl = 0.f;

    #pragma unroll 8
    for (int i = 0; i < ROWS_PER_WARP; i++) {
        const int r  = r0 + i;                 // global row = b*N_POOL + p
        const int p  = r & (N_POOL - 1);
        const int c  = p & 127;
        const int ow = (p >> 7) & 31;
        const int oh = p >> 12;
        const int base = b * N_IN + oh * (2 * W * C) + ow * (2 * C) + c;

        // fused 2x2 maxpool (lane-uniform broadcast loads)
        const float u0 = __ldg(u_c + base);
        const float u1 = __ldg(u_c + base + C);
        const float u2 = __ldg(u_c + base + W * C);
        const float u3 = __ldg(u_c + base + W * C + C);
        const float bu = fmaxf(fmaxf(u0, u1), fmaxf(u2, u3));

        const float l0 = __ldg(l_c + base);
        const float l1 = __ldg(l_c + base + C);
        const float l2 = __ldg(l_c + base + W * C);
        const float l3 = __ldg(l_c + base + W * C + C);
        const float bl = fmaxf(fmaxf(l0, l1), fmaxf(l2, l3));

        // coalesced weight rows: lane = output index o (128B/warp/row)
        const float wu = __ldg(w_out_u + r * N_OUT + lane);
        const float wl = __ldg(w_out_l + r * N_OUT + lane);

        accu += fmaxf(wu, 0.f) * bu + fminf(wu, 0.f) * bl;
        accl += fmaxf(wl, 0.f) * bl + fminf(wl, 0.f) * bu;
    }

    // block reduction across the 8 warps (all rows in a block share one batch:
    // 128 rows/block and 131072 % 128 == 0)
    __shared__ float su[8][32];
    __shared__ float sl[8][32];
    su[warp][lane] = accu;
    sl[warp][lane] = accl;
    __syncthreads();

    if (warp == 0) {
        float s = 0.f;
        #pragma unroll
        for (int k = 0; k < 8; k++) s += su[k][lane];
        g_partial[blockIdx.x * 64 + lane] = s;
    } else if (warp == 1) {
        float s = 0.f;
        #pragma unroll
        for (int k = 0; k < 8; k++) s += sl[k][lane];
        g_partial[blockIdx.x * 64 + 32 + lane] = s;
    }
}

// ---------------------------------------------------------------------------
// Phase 3: parallel finalize. 128 outputs, one WARP per output; each lane
// sums 32 partials (L2-warm), warp shfl-reduce, then slot = sum + bias.
// 4 blocks x 1024 threads = 128 warps.
// ---------------------------------------------------------------------------
__global__ void __launch_bounds__(1024)
finalize_kernel(float* __restrict__ out,
                const float* __restrict__ b_out_u,
                const float* __restrict__ b_out_l) {
    const int gwarp = blockIdx.x * 32 + (threadIdx.x >> 5);  // 0..127
    const int lane  = threadIdx.x & 31;

    // output decomposition: gwarp = sel*64 + b*32 + o
    const int o   = gwarp & 31;
    const int b   = (gwarp >> 5) & 1;
    const int sel = gwarp >> 6;            // 0 = upper, 1 = lower

    // blocks for batch b: [b*1024, (b+1)*1024)
    const int blk0 = b * (RGRID / 2);
    float s = 0.f;
    #pragma unroll
    for (int j = 0; j < (RGRID / 2) / 32; j++) {       // 32 iters
        const int blk = blk0 + j * 32 + lane;
        s += g_partial[blk * 64 + sel * 32 + o];
    }
    // warp reduction
    #pragma unroll
    for (int d = 16; d > 0; d >>= 1)
        s += __shfl_xor_sync(0xFFFFFFFFu, s, d);

    if (lane == 0) {
        if (sel == 0)
            out[OFF1 + b * N_OUT + o] = s + __ldg(b_out_u + b * N_OUT + o);
        else
            out[OFF3 + b * N_OUT + o] = s + __ldg(b_out_l + b * N_OUT + o);
    }
}

extern "C" void kernel_launch(void* const* d_in, const int* in_sizes, int n_in,
                              void* d_out, int out_size) {
    // metadata order: y, x_0, u_c, l_c, w_out_u, b_out_u, w_out_l, b_out_l
    const float* u_c     = (const float*)d_in[2];
    const float* l_c     = (const float*)d_in[3];
    const float* w_out_u = (const float*)d_in[4];
    const float* b_out_u = (const float*)d_in[5];
    const float* w_out_l = (const float*)d_in[6];
    const float* b_out_l = (const float*)d_in[7];
    float* out = (float*)d_out;

    zero_kernel<<<ZGRID, NTHREADS>>>(out);
    reduce_kernel<<<RGRID, NTHREADS>>>(u_c, l_c, w_out_u, w_out_l);
    finalize_kernel<<<4, 1024>>>(out, b_out_u, b_out_l);
}

// round 5
// speedup vs baseline: 1.5808x; 1.3909x over previous
#include <cuda_runtime.h>

// Problem constants (fixed shapes)
#define BATCH   2
#define H       64
#define W       64
#define C       128
#define N_IN    (H * W * C)            // 524288
#define N_POOL  ((H/2) * (W/2) * C)    // 131072
#define N_OUT   32

// Output layout (concatenated, all float32):
//   [0, OFF1)       w_zero #1 : 33,554,432
//   [OFF1, OFF2)    b_out_u_  : 64
//   [OFF2, OFF3)    w_zero #2 : 33,554,432
//   [OFF3, TOTAL)   b_out_l_  : 64
#define OFF1    (BATCH * N_IN * N_OUT)         // 33554432
#define OFF2    (OFF1 + BATCH * N_OUT)         // 33554496
#define OFF3    (OFF2 + BATCH * N_IN * N_OUT)  // 67108928
#define TOTAL   (OFF3 + BATCH * N_OUT)         // 67108992
#define TOTAL4   (TOTAL / 4)                   // 16777248
#define SKIP_BEG (OFF1 / 4)                    // 8388608  (bias slot 1, 16 float4s)
#define SKIP_END (OFF2 / 4)                    // 8388624
#define ZTAIL4   (OFF3 / 4)                    // 16777232 (bias slot 2 = final tail)

#define NTHREADS 256
#define ZGRID    1184                          // 148 SMs x 8 blocks: one wave
#define RGRID    2048                          // one pool window per block

// ---------------------------------------------------------------------------
// Phase 1: pure write stream. Zero [0, ZTAIL4) float4s except bias slot 1.
// Block 0 seeds both bias slots with the input biases (atomics add onto them).
// ---------------------------------------------------------------------------
__global__ void __launch_bounds__(NTHREADS)
zero_kernel(float* __restrict__ out,
            const float* __restrict__ b_out_u,
            const float* __restrict__ b_out_l) {
    if (blockIdx.x == 0 && threadIdx.x < BATCH * N_OUT) {
        out[OFF1 + threadIdx.x] = b_out_u[threadIdx.x];
        out[OFF3 + threadIdx.x] = b_out_l[threadIdx.x];
    }
    float4* o4 = reinterpret_cast<float4*>(out);
    const float4 z = make_float4(0.f, 0.f, 0.f, 0.f);
    const int stride = ZGRID * NTHREADS;
    for (int i = blockIdx.x * NTHREADS + threadIdx.x; i < ZTAIL4; i += stride) {
        if ((unsigned)(i - SKIP_BEG) >= (unsigned)(SKIP_END - SKIP_BEG))
            __stcs(&o4[i], z);                 // streaming store hint
    }
}

// ---------------------------------------------------------------------------
// Phase 2: pure read stream. Each block = one 2x2 pool window x 128 channels
// (rows r = blockIdx*128 + c, c in [0,128)). Stage 1 pools bounds into smem
// with coalesced loads; stage 2 streams weights as float4.
// ---------------------------------------------------------------------------
__global__ void __launch_bounds__(NTHREADS)
reduce_kernel(float* __restrict__ out,
              const float* __restrict__ u_c,
              const float* __restrict__ l_c,
              const float* __restrict__ w_out_u,
              const float* __restrict__ w_out_l) {
    __shared__ float bu_s[128];
    __shared__ float bl_s[128];
    __shared__ float4 su[8][8];                // [warp][oq] partial accu
    __shared__ float4 sl[8][8];

    const int t    = threadIdx.x;
    const int bIdx = blockIdx.x;
    const int b    = bIdx >> 10;               // 1024 windows per batch
    const int widx = bIdx & 1023;              // window index within batch
    const int oh   = widx >> 5;
    const int ow   = widx & 31;
    const int base0 = b * N_IN + oh * (2 * W * C) + ow * (2 * C);

    // ---- stage 1: cooperative coalesced pooling into smem ----
    if (t < 128) {
        const int c = t;
        const float a0 = u_c[base0 + c];
        const float a1 = u_c[base0 + C + c];
        const float a2 = u_c[base0 + W * C + c];
        const float a3 = u_c[base0 + W * C + C + c];
        bu_s[c] = fmaxf(fmaxf(a0, a1), fmaxf(a2, a3));
    } else {
        const int c = t - 128;
        const float a0 = l_c[base0 + c];
        const float a1 = l_c[base0 + C + c];
        const float a2 = l_c[base0 + W * C + c];
        const float a3 = l_c[base0 + W * C + C + c];
        bl_s[c] = fmaxf(fmaxf(a0, a1), fmaxf(a2, a3));
    }
    __syncthreads();

    // ---- stage 2: vectorized weight streaming ----
    // warp w handles channels c in [w*16, w*16+16).
    // lane = row_sub*8 + oq: row_sub in [0,4), oq in [0,8). Per iteration j,
    // lane covers row c = w*16 + j*4 + row_sub, outputs o = oq*4..oq*4+3.
    const int warp    = t >> 5;
    const int lane    = t & 31;
    const int row_sub = lane >> 3;
    const int oq      = lane & 7;

    float4 accu = make_float4(0.f, 0.f, 0.f, 0.f);
    float4 accl = make_float4(0.f, 0.f, 0.f, 0.f);

    #pragma unroll
    for (int j = 0; j < 4; j++) {
        const int c = warp * 16 + j * 4 + row_sub;
        const int r = bIdx * 128 + c;          // global row = b*N_POOL + p
        const float bu = bu_s[c];
        const float bl = bl_s[c];
        // 512 B contiguous per warp per load (LDG.128 x32 lanes)
        const float4 wu = *reinterpret_cast<const float4*>(w_out_u + (size_t)r * N_OUT + oq * 4);
        const float4 wl = *reinterpret_cast<const float4*>(w_out_l + (size_t)r * N_OUT + oq * 4);

        accu.x += fmaxf(wu.x, 0.f) * bu + fminf(wu.x, 0.f) * bl;
        accu.y += fmaxf(wu.y, 0.f) * bu + fminf(wu.y, 0.f) * bl;
        accu.z += fmaxf(wu.z, 0.f) * bu + fminf(wu.z, 0.f) * bl;
        accu.w += fmaxf(wu.w, 0.f) * bu + fminf(wu.w, 0.f) * bl;

        accl.x += fmaxf(wl.x, 0.f) * bl + fminf(wl.x, 0.f) * bu;
        accl.y += fmaxf(wl.y, 0.f) * bl + fminf(wl.y, 0.f) * bu;
        accl.z += fmaxf(wl.z, 0.f) * bl + fminf(wl.z, 0.f) * bu;
        accl.w += fmaxf(wl.w, 0.f) * bl + fminf(wl.w, 0.f) * bu;
    }

    // reduce across row_sub (lane bits 3,4): lanes 0..7 end with warp totals
    #pragma unroll
    for (int d = 8; d < 32; d <<= 1) {
        accu.x += __shfl_xor_sync(0xFFFFFFFFu, accu.x, d);
        accu.y += __shfl_xor_sync(0xFFFFFFFFu, accu.y, d);
        accu.z += __shfl_xor_sync(0xFFFFFFFFu, accu.z, d);
        accu.w += __shfl_xor_sync(0xFFFFFFFFu, accu.w, d);
        accl.x += __shfl_xor_sync(0xFFFFFFFFu, accl.x, d);
        accl.y += __shfl_xor_sync(0xFFFFFFFFu, accl.y, d);
        accl.z += __shfl_xor_sync(0xFFFFFFFFu, accl.z, d);
        accl.w += __shfl_xor_sync(0xFFFFFFFFu, accl.w, d);
    }
    if (row_sub == 0) {
        su[warp][oq] = accu;
        sl[warp][oq] = accl;
    }
    __syncthreads();

    // block reduction over the 8 warps, then 64 atomicAdds to bias slots
    if (warp == 0) {
        // lane = o in [0,32): oq = o>>2, comp = o&3
        const int o = lane;
        const float* p = reinterpret_cast<const float*>(&su[0][0]) + (o >> 2) * 4 + (o & 3);
        float s = 0.f;
        #pragma unroll
        for (int k = 0; k < 8; k++) s += p[k * 32];
        atomicAdd(&out[OFF1 + b * N_OUT + o], s);
    } else if (warp == 1) {
        const int o = lane;
        const float* p = reinterpret_cast<const float*>(&sl[0][0]) + (o >> 2) * 4 + (o & 3);
        float s = 0.f;
        #pragma unroll
        for (int k = 0; k < 8; k++) s += p[k * 32];
        atomicAdd(&out[OFF3 + b * N_OUT + o], s);
    }
}

extern "C" void kernel_launch(void* const* d_in, const int* in_sizes, int n_in,
                              void* d_out, int out_size) {
    // metadata order: y, x_0, u_c, l_c, w_out_u, b_out_u, w_out_l, b_out_l
    const float* u_c     = (const float*)d_in[2];
    const float* l_c     = (const float*)d_in[3];
    const float* w_out_u = (const float*)d_in[4];
    const float* b_out_u = (const float*)d_in[5];
    const float* w_out_l = (const float*)d_in[6];
    const float* b_out_l = (const float*)d_in[7];
    float* out = (float*)d_out;

    zero_kernel<<<ZGRID, NTHREADS>>>(out, b_out_u, b_out_l);
    reduce_kernel<<<RGRID, NTHREADS>>>(out, u_c, l_c, w_out_u, w_out_l);
}